// round 7
// baseline (speedup 1.0000x reference)
#include <cuda_runtime.h>

typedef unsigned long long ull;

// 201 MB ping-pong scratch (allocation-free rule: __device__ global)
__device__ float g_buf[16u * 3u * 1024u * 1024u];
// pre-packed (w,w) f32x2 weights, layout [ci][kx][s=co*5+ky] padded to 16 (16B-aligned)
__device__ ull   g_wpack[240];

__device__ __forceinline__ ull pack2(float lo, float hi) {
    ull r;
    asm("mov.b64 %0, {%1, %2};" : "=l"(r) : "f"(lo), "f"(hi));
    return r;
}
__device__ __forceinline__ float2 unpack2(ull v) {
    float2 r;
    asm("mov.b64 {%0, %1}, %2;" : "=f"(r.x), "=f"(r.y) : "l"(v));
    return r;
}
// packed fp32x2 FMA (FFMA2) -- only reachable via PTX fma.rn.f32x2
__device__ __forceinline__ void fma2(ull& d, ull a, ull b) {
    asm("fma.rn.f32x2 %0, %1, %2, %0;" : "+l"(d) : "l"(a), "l"(b));
}

__device__ __forceinline__ void cp16(void* dst_smem, const void* src_gmem) {
    unsigned d = (unsigned)__cvta_generic_to_shared(dst_smem);
    asm volatile("cp.async.cg.shared.global [%0], [%1], 16;" :: "r"(d), "l"(src_gmem));
}
__device__ __forceinline__ void cp4(void* dst_smem, const void* src_gmem) {
    unsigned d = (unsigned)__cvta_generic_to_shared(dst_smem);
    asm volatile("cp.async.ca.shared.global [%0], [%1], 4;" :: "r"(d), "l"(src_gmem));
}
__device__ __forceinline__ void cp_commit() {
    asm volatile("cp.async.commit_group;");
}
__device__ __forceinline__ void cp_wait_all() {
    asm volatile("cp.async.wait_group 0;" ::: "memory");
}

// prep: broadcast-pack weights once; W is OIHW [co][ci][ky][kx] = [3][3][5][5]
__global__ void pack_w(const float* __restrict__ W) {
    int i = threadIdx.x;
    if (i >= 240) return;
    int ci = i / 80;
    int r  = i - ci * 80;
    int kx = r / 16;
    int s  = r - kx * 16;
    float w = 0.0f;
    if (s < 15) {
        int co = s / 5;
        int ky = s - co * 5;
        w = W[co * 75 + ci * 25 + ky * 5 + kx];
    }
    g_wpack[i] = pack2(w, w);
}

// 8 packed FMAs: one weight pair against window rows base..base+7
__device__ __forceinline__ void fma8(ull* accrow, const ull* base, ull w) {
    #pragma unroll
    for (int p = 0; p < 8; ++p)
        fma2(accrow[p], base[p], w);
}

// 12 conflict-free LDS.64: one column window, all pair-rows
__device__ __forceinline__ void load_window(ull* rv, const float2* colbase, int kx) {
    #pragma unroll
    for (int p = 0; p < 12; ++p)
        rv[p] = *reinterpret_cast<const ull*>(colbase + p * 132 + kx);
}

// one (ci,kx) chunk: 8 weight fetches (LDS.128 pairs) + 120 FFMA2,
// s = co*5+ky ascending -> identical accumulation order to R5/R6
__device__ __forceinline__ void fchunk(ull (*acc)[8], const ull* rv, const ull* wrow) {
    const ulonglong2* wv = reinterpret_cast<const ulonglong2*>(wrow);
    #pragma unroll
    for (int j = 0; j < 7; ++j) {
        ulonglong2 q = wv[j];
        const int s0 = 2 * j;
        const int s1 = 2 * j + 1;
        fma8(acc[s0 / 5], rv + (s0 % 5), q.x);
        fma8(acc[s1 / 5], rv + (s1 % 5), q.y);
    }
    fma8(acc[2], rv + 4, wrow[14]);   // s=14 -> co=2, ky=4
}

// SMEM layout (dynamic):
//   pbuf: float2[3][12][132]  paired tile   (38016 B)
//   sbuf: float [3][20][136]  plain staging (32640 B)  rows r = gmem row (rb+r-2)&1023
//         cols [0..127] = gmem xb..xb+127 ; [128,129] = xb-2,xb-1 ; [130,131] = xb+128,xb+129
//   wS  : ull[240]            weights      (1920 B)
#define PBUF_BYTES 38016
#define SBUF_BYTES 32640
#define DSMEM_BYTES (PBUF_BYTES + SBUF_BYTES + 1920)

// Block: 128 threads, processes NT=4 row-tiles (128 cols x 16 rows x 3 ch each).
// cp.async stages tile t+1 during tile t's compute; repack sbuf->pbuf between tiles.
__global__ void __launch_bounds__(128, 3) ca_step(const float* __restrict__ src,
                                                  float* __restrict__ dst)
{
    extern __shared__ __align__(16) char dsm[];
    float2 (*pbuf)[12][132] = reinterpret_cast<float2(*)[12][132]>(dsm);
    float  (*sbuf)[20][136] = reinterpret_cast<float(*)[20][136]>(dsm + PBUF_BYTES);
    ull*    wS              = reinterpret_cast<ull*>(dsm + PBUF_BYTES + SBUF_BYTES);

    const int tid     = threadIdx.x;
    const int xb      = blockIdx.x * 128;
    const int rb_base = blockIdx.y * 64;
    const int img     = blockIdx.z;

    // ---- issue cp.async for tile 0 ASAP ----
    {
        const int rbn = rb_base;
        #pragma unroll 1
        for (int k = 0; k < 15; ++k) {           // interior: 1920 16B chunks
            int i   = tid + k * 128;
            int ch  = i / 640;
            int rem = i - ch * 640;
            int r   = rem >> 5;
            int c   = rem & 31;
            const float* sp = src + (((size_t)(img * 3 + ch)) << 20)
                            + (((rbn + r - 2) & 1023) << 10) + xb + c * 4;
            cp16(&sbuf[ch][r][c * 4], sp);
        }
        {                                         // halo: 240 4B items, 2 trips
            int i = tid;
            #pragma unroll
            for (int trip = 0; trip < 2; ++trip) {
                if (i < 240) {
                    int ch  = i / 80;
                    int rem = i - ch * 80;
                    int r   = rem >> 2;
                    int j   = rem & 3;
                    int gcol = ((j < 2) ? (xb - 2 + j) : (xb + 126 + j)) & 1023;
                    const float* sp = src + (((size_t)(img * 3 + ch)) << 20)
                                    + (((rbn + r - 2) & 1023) << 10) + gcol;
                    cp4(&sbuf[ch][r][128 + j], sp);
                }
                i += 128;
            }
        }
        cp_commit();
    }

    // ---- weights -> smem ----
    if (tid < 120) {
        wS[tid]       = g_wpack[tid];
        wS[tid + 120] = g_wpack[tid + 120];
    }

    cp_wait_all();
    __syncthreads();

    const float2* cb0 = &pbuf[0][0][tid];
    const float2* cb1 = &pbuf[1][0][tid];
    const float2* cb2 = &pbuf[2][0][tid];
    const int col = xb + tid;

    #pragma unroll 1
    for (int t = 0; t < 4; ++t) {
        // ---- repack sbuf -> pbuf (paired layout) ----
        #pragma unroll 1
        for (int k = 0; k < 9; ++k) {            // interior: 1152 4-col groups
            int i   = tid + k * 128;
            int ch  = i / 384;
            int rem = i - ch * 384;
            int p   = rem >> 5;
            int g   = rem & 31;
            float4 a = *reinterpret_cast<const float4*>(&sbuf[ch][p][g * 4]);
            float4 b = *reinterpret_cast<const float4*>(&sbuf[ch][p + 8][g * 4]);
            float4* d = reinterpret_cast<float4*>(&pbuf[ch][p][2 + g * 4]);
            d[0] = make_float4(a.x, b.x, a.y, b.y);
            d[1] = make_float4(a.z, b.z, a.w, b.w);
        }
        {                                         // halo: 144 pairs, 2 trips
            int i = tid;
            #pragma unroll
            for (int trip = 0; trip < 2; ++trip) {
                if (i < 144) {
                    int ch  = i / 48;
                    int rem = i - ch * 48;
                    int p   = rem >> 2;
                    int j   = rem & 3;
                    int xi  = (j < 2) ? j : (j + 128);
                    pbuf[ch][p][xi] = make_float2(sbuf[ch][p][128 + j],
                                                  sbuf[ch][p + 8][128 + j]);
                }
                i += 128;
            }
        }
        __syncthreads();   // repack done (sbuf free, pbuf ready)

        // ---- prefetch tile t+1 into staging while we compute tile t ----
        if (t < 3) {
            const int rbn = rb_base + (t + 1) * 16;
            #pragma unroll 1
            for (int k = 0; k < 15; ++k) {
                int i   = tid + k * 128;
                int ch  = i / 640;
                int rem = i - ch * 640;
                int r   = rem >> 5;
                int c   = rem & 31;
                const float* sp = src + (((size_t)(img * 3 + ch)) << 20)
                                + (((rbn + r - 2) & 1023) << 10) + xb + c * 4;
                cp16(&sbuf[ch][r][c * 4], sp);
            }
            int i = tid;
            #pragma unroll
            for (int trip = 0; trip < 2; ++trip) {
                if (i < 240) {
                    int ch  = i / 80;
                    int rem = i - ch * 80;
                    int r   = rem >> 2;
                    int j   = rem & 3;
                    int gcol = ((j < 2) ? (xb - 2 + j) : (xb + 126 + j)) & 1023;
                    const float* sp = src + (((size_t)(img * 3 + ch)) << 20)
                                    + (((rbn + r - 2) & 1023) << 10) + gcol;
                    cp4(&sbuf[ch][r][128 + j], sp);
                }
                i += 128;
            }
            cp_commit();
        }

        // ---- conv accumulation: 3 out-channels x 8 row-pairs, packed f32x2 ----
        ull acc[3][8];
        #pragma unroll
        for (int co = 0; co < 3; ++co)
            #pragma unroll
            for (int p = 0; p < 8; ++p)
                acc[co][p] = 0ull;

        ull rvA[12], rvB[12];
        // 15 chunks (ci,kx), 2-deep pipeline (R6-proven FMA order)
        load_window(rvA, cb0, 0);
        load_window(rvB, cb0, 1);  fchunk(acc, rvA, &wS[0 * 80 + 0 * 16]);
        load_window(rvA, cb0, 2);  fchunk(acc, rvB, &wS[0 * 80 + 1 * 16]);
        load_window(rvB, cb0, 3);  fchunk(acc, rvA, &wS[0 * 80 + 2 * 16]);
        load_window(rvA, cb0, 4);  fchunk(acc, rvB, &wS[0 * 80 + 3 * 16]);
        load_window(rvB, cb1, 0);  fchunk(acc, rvA, &wS[0 * 80 + 4 * 16]);
        load_window(rvA, cb1, 1);  fchunk(acc, rvB, &wS[1 * 80 + 0 * 16]);
        load_window(rvB, cb1, 2);  fchunk(acc, rvA, &wS[1 * 80 + 1 * 16]);
        load_window(rvA, cb1, 3);  fchunk(acc, rvB, &wS[1 * 80 + 2 * 16]);
        load_window(rvB, cb1, 4);  fchunk(acc, rvA, &wS[1 * 80 + 3 * 16]);
        load_window(rvA, cb2, 0);  fchunk(acc, rvB, &wS[1 * 80 + 4 * 16]);
        load_window(rvB, cb2, 1);  fchunk(acc, rvA, &wS[2 * 80 + 0 * 16]);
        load_window(rvA, cb2, 2);  fchunk(acc, rvB, &wS[2 * 80 + 1 * 16]);
        load_window(rvB, cb2, 3);  fchunk(acc, rvA, &wS[2 * 80 + 2 * 16]);
        load_window(rvA, cb2, 4);  fchunk(acc, rvB, &wS[2 * 80 + 3 * 16]);
                                   fchunk(acc, rvA, &wS[2 * 80 + 4 * 16]);

        // ---- epilogue: out = clip(x + 0.1*relu(y), 0, 1) ----
        const int rb = rb_base + t * 16;
        #pragma unroll
        for (int co = 0; co < 3; ++co) {
            float* ob = dst + (((size_t)(img * 3 + co)) << 20) + col;
            #pragma unroll
            for (int p = 0; p < 8; ++p) {
                float2 y  = unpack2(acc[co][p]);
                float2 xp = pbuf[co][p + 2][tid + 2];   // (row rb+p, row rb+p+8)
                ob[(rb + p)     << 10] = __saturatef(fmaf(fmaxf(y.x, 0.0f), 0.1f, xp.x));
                ob[(rb + p + 8) << 10] = __saturatef(fmaf(fmaxf(y.y, 0.0f), 0.1f, xp.y));
            }
        }

        // staging for t+1 must be complete & visible; pbuf(t) reads all done
        cp_wait_all();
        __syncthreads();
    }
}

extern "C" void kernel_launch(void* const* d_in, const int* in_sizes, int n_in,
                              void* d_out, int out_size)
{
    const float* x = (const float*)d_in[0];
    const float* W = (const float*)d_in[1];
    float* out = (float*)d_out;

    float* scratch = nullptr;
    cudaGetSymbolAddress((void**)&scratch, g_buf);

    cudaFuncSetAttribute(ca_step, cudaFuncAttributeMaxDynamicSharedMemorySize,
                         DSMEM_BYTES);

    pack_w<<<1, 256>>>(W);

    dim3 grid(8, 16, 16);   // 1024/128 cols, 1024/(16*4) row-groups, 16 images
    dim3 block(128);

    const float* src = x;
    for (int s = 0; s < 10; ++s) {
        float* dst = (s & 1) ? out : scratch;  // step 9 (last) lands in d_out
        ca_step<<<grid, block, DSMEM_BYTES>>>(src, dst);
        src = dst;
    }
}

// round 8
// speedup vs baseline: 1.0449x; 1.0449x over previous
#include <cuda_runtime.h>

typedef unsigned long long ull;

#define SLOTS 516   // 512 pair-rows + 2-slot swapped extension each end

// pair-layout ping-pong buffers: P[img][ch][slot][col], slot = pr+2,
// pair pr = (row pr, row pr+512); ~203 MB each (allocation-free rule)
__device__ float2 g_p0[16 * 3 * SLOTS * 1024];
__device__ float2 g_p1[16 * 3 * SLOTS * 1024];
// pre-packed (w,w) f32x2 weights, layout [ci][kx][s=co*5+ky] padded to 16
__device__ ull    g_wpack[240];

__device__ __forceinline__ ull pack2(float lo, float hi) {
    ull r;
    asm("mov.b64 %0, {%1, %2};" : "=l"(r) : "f"(lo), "f"(hi));
    return r;
}
__device__ __forceinline__ float2 unpack2(ull v) {
    float2 r;
    asm("mov.b64 {%0, %1}, %2;" : "=f"(r.x), "=f"(r.y) : "l"(v));
    return r;
}
// packed fp32x2 FMA (FFMA2) -- only reachable via PTX fma.rn.f32x2
__device__ __forceinline__ void fma2(ull& d, ull a, ull b) {
    asm("fma.rn.f32x2 %0, %1, %2, %0;" : "+l"(d) : "l"(a), "l"(b));
}
__device__ __forceinline__ void cp16(void* dst_smem, const void* src_gmem) {
    unsigned d = (unsigned)__cvta_generic_to_shared(dst_smem);
    asm volatile("cp.async.cg.shared.global [%0], [%1], 16;" :: "r"(d), "l"(src_gmem));
}
__device__ __forceinline__ void cp_commit() {
    asm volatile("cp.async.commit_group;");
}
__device__ __forceinline__ void cp_wait_all() {
    asm volatile("cp.async.wait_group 0;" ::: "memory");
}

// prep: broadcast-pack weights once; W is OIHW [co][ci][ky][kx] = [3][3][5][5]
__global__ void pack_w(const float* __restrict__ W) {
    int i = threadIdx.x;
    if (i >= 240) return;
    int ci = i / 80;
    int r  = i - ci * 80;
    int kx = r / 16;
    int s  = r - kx * 16;
    float w = 0.0f;
    if (s < 15) {
        int co = s / 5;
        int ky = s - co * 5;
        w = W[co * 75 + ci * 25 + ky * 5 + kx];
    }
    g_wpack[i] = pack2(w, w);
}

// 8 packed FMAs: one weight pair against window rows base..base+7
__device__ __forceinline__ void fma8(ull* accrow, const ull* base, ull w) {
    #pragma unroll
    for (int p = 0; p < 8; ++p)
        fma2(accrow[p], base[p], w);
}
// 12 conflict-free LDS.64: one column window, all pair-rows
__device__ __forceinline__ void load_window(ull* rv, const float2* colbase, int kx) {
    #pragma unroll
    for (int p = 0; p < 12; ++p)
        rv[p] = *reinterpret_cast<const ull*>(colbase + p * 132 + kx);
}
// one (ci,kx) chunk: 8 weight LDS.128 pairs + 120 FFMA2 (R5/R6-proven order)
__device__ __forceinline__ void fchunk(ull (*acc)[8], const ull* rv, const ull* wrow) {
    const ulonglong2* wv = reinterpret_cast<const ulonglong2*>(wrow);
    #pragma unroll
    for (int j = 0; j < 7; ++j) {
        ulonglong2 q = wv[j];
        const int s0 = 2 * j;
        const int s1 = 2 * j + 1;
        fma8(acc[s0 / 5], rv + (s0 % 5), q.x);
        fma8(acc[s1 / 5], rv + (s1 % 5), q.y);
    }
    fma8(acc[2], rv + 4, wrow[14]);   // s=14 -> co=2, ky=4
}

// halo for the normal-layout loader (step 0): 144 items = 3ch x 12p x 4 wrap cols
__device__ __forceinline__ void halo_loadN(const float* __restrict__ src,
                                           float2 (*smx)[12][132],
                                           int i, int xb, int rb, int img)
{
    int ch  = i / 48;
    int rem = i - ch * 48;
    int p   = rem >> 2;
    int j   = rem & 3;
    int xi  = (j < 2) ? j : (j + 128);
    int col = (xb + xi - 2) & 1023;
    int rA  = (rb + p - 2) & 1023;
    int rB  = (rA + 512) & 1023;
    const float* base = src + (((size_t)(img * 3 + ch)) << 20);
    smx[ch][p][xi] = make_float2(__ldg(base + (rA << 10) + col),
                                 __ldg(base + (rB << 10) + col));
}

// Block: 128 threads. Tile: 128 cols x 8 pair-rows (= 16 image rows, 512 apart)
// x 3 channels. Thread owns ONE column; 8 acc pairs x 3 co; window = 12 pair-rows.
// smx[ch][p][xi] = pair (row rb+p-2, row rb+p+510), xi-2 = col offset.
// LOADP: smx filled by pure cp.async from pair-layout gmem (zero repack).
template <bool LOADP, bool STOREP>
__global__ void __launch_bounds__(128, 4) ca_step(const float*  __restrict__ srcN,
                                                  const float2* __restrict__ srcP,
                                                  float*        __restrict__ dstN,
                                                  float2*       __restrict__ dstP)
{
    __shared__ __align__(16) float2 smx[3][12][132];
    __shared__ __align__(16) ull    wS[240];

    const int tid = threadIdx.x;
    const int xb  = blockIdx.x * 128;
    const int rb  = blockIdx.y * 8;    // pair-row base, 0..504
    const int img = blockIdx.z;

    if (LOADP) {
        // 2376 cp16 pieces: 3ch x 12 pair-rows x 66 (1 left-halo, 64 interior, 1 right-halo)
        #pragma unroll 1
        for (int k = 0; k < 19; ++k) {
            int i = tid + k * 128;
            if (i < 2376) {
                int ch    = (i >= 1584) ? 2 : ((i >= 792) ? 1 : 0);
                int rem   = i - ch * 792;
                int p     = (rem * 1986) >> 17;          // rem/66
                int piece = rem - p * 66;
                const float2* rowb = srcP
                    + ((size_t)((img * 3 + ch) * SLOTS + rb + p)) * 1024;  // slot = (rb+p-2)+2
                int xi, colc;
                if (piece == 0)       { xi = 0;   colc = (xb - 2) & 1023;   }
                else if (piece == 65) { xi = 130; colc = (xb + 128) & 1023; }
                else                  { xi = piece * 2; colc = xb + (piece - 1) * 2; }
                cp16(&smx[ch][p][xi], rowb + colc);
            }
        }
        cp_commit();
    } else {
        // normal-layout loader (step 0): pairs (r, r+512), R6-style shuffle
        const int v  = tid & 31;
        const int pq = tid >> 5;
        #pragma unroll
        for (int ch = 0; ch < 3; ++ch) {
            const float* cbase = srcN + (((size_t)(img * 3 + ch)) << 20) + xb + v * 4;
            #pragma unroll
            for (int k = 0; k < 3; ++k) {
                int p  = k * 4 + pq;
                int rA = (rb + p - 2) & 1023;
                int rB = (rA + 512) & 1023;
                float4 a = *reinterpret_cast<const float4*>(cbase + (rA << 10));
                float4 b = *reinterpret_cast<const float4*>(cbase + (rB << 10));
                float4* s = reinterpret_cast<float4*>(&smx[ch][p][2 + v * 4]);
                s[0] = make_float4(a.x, b.x, a.y, b.y);
                s[1] = make_float4(a.z, b.z, a.w, b.w);
            }
        }
        halo_loadN(srcN, smx, tid, xb, rb, img);
        if (tid < 16)
            halo_loadN(srcN, smx, tid + 128, xb, rb, img);
    }

    // ---- weights -> smem ----
    if (tid < 120) {
        wS[tid]       = g_wpack[tid];
        wS[tid + 120] = g_wpack[tid + 120];
    }
    if (LOADP) cp_wait_all();
    __syncthreads();

    // ---- conv accumulation: 3 out-channels x 8 pair-rows, packed f32x2 ----
    ull acc[3][8];
    #pragma unroll
    for (int co = 0; co < 3; ++co)
        #pragma unroll
        for (int p = 0; p < 8; ++p)
            acc[co][p] = 0ull;

    const float2* cb0 = &smx[0][0][tid];
    const float2* cb1 = &smx[1][0][tid];
    const float2* cb2 = &smx[2][0][tid];

    ull rvA[12], rvB[12];
    // 15 chunks (ci,kx), 2-deep pipeline (R6-proven)
    load_window(rvA, cb0, 0);
    load_window(rvB, cb0, 1);  fchunk(acc, rvA, &wS[0 * 80 + 0 * 16]);
    load_window(rvA, cb0, 2);  fchunk(acc, rvB, &wS[0 * 80 + 1 * 16]);
    load_window(rvB, cb0, 3);  fchunk(acc, rvA, &wS[0 * 80 + 2 * 16]);
    load_window(rvA, cb0, 4);  fchunk(acc, rvB, &wS[0 * 80 + 3 * 16]);
    load_window(rvB, cb1, 0);  fchunk(acc, rvA, &wS[0 * 80 + 4 * 16]);
    load_window(rvA, cb1, 1);  fchunk(acc, rvB, &wS[1 * 80 + 0 * 16]);
    load_window(rvB, cb1, 2);  fchunk(acc, rvA, &wS[1 * 80 + 1 * 16]);
    load_window(rvA, cb1, 3);  fchunk(acc, rvB, &wS[1 * 80 + 2 * 16]);
    load_window(rvB, cb1, 4);  fchunk(acc, rvA, &wS[1 * 80 + 3 * 16]);
    load_window(rvA, cb2, 0);  fchunk(acc, rvB, &wS[1 * 80 + 4 * 16]);
    load_window(rvB, cb2, 1);  fchunk(acc, rvA, &wS[2 * 80 + 0 * 16]);
    load_window(rvA, cb2, 2);  fchunk(acc, rvB, &wS[2 * 80 + 1 * 16]);
    load_window(rvB, cb2, 3);  fchunk(acc, rvA, &wS[2 * 80 + 2 * 16]);
    load_window(rvA, cb2, 4);  fchunk(acc, rvB, &wS[2 * 80 + 3 * 16]);
                               fchunk(acc, rvA, &wS[2 * 80 + 4 * 16]);

    // ---- epilogue: out = clip(x + 0.1*relu(y), 0, 1) ----
    const int col = xb + tid;
    #pragma unroll
    for (int co = 0; co < 3; ++co) {
        float2* obP = STOREP
            ? dstP + ((size_t)((img * 3 + co) * SLOTS + rb + 2)) * 1024 + col : nullptr;
        float*  obN = STOREP
            ? nullptr : dstN + (((size_t)(img * 3 + co)) << 20) + col;
        #pragma unroll
        for (int p = 0; p < 8; ++p) {
            float2 y  = unpack2(acc[co][p]);
            float2 xp = smx[co][p + 2][tid + 2];   // pair (row rb+p, row rb+p+512)
            float lo = __saturatef(fmaf(fmaxf(y.x, 0.0f), 0.1f, xp.x));
            float hi = __saturatef(fmaf(fmaxf(y.y, 0.0f), 0.1f, xp.y));
            if (STOREP) {
                obP[p * 1024] = make_float2(lo, hi);
                // swapped extension copies at the 0/512 wrap seam
                if (rb == 0 && p < 2)
                    dstP[((size_t)((img * 3 + co) * SLOTS + 514 + p)) * 1024 + col]
                        = make_float2(hi, lo);
                if (rb == 504 && p >= 6)
                    dstP[((size_t)((img * 3 + co) * SLOTS + (p - 6))) * 1024 + col]
                        = make_float2(hi, lo);
            } else {
                obN[(rb + p)       << 10] = lo;
                obN[(rb + p + 512) << 10] = hi;
            }
        }
    }
}

extern "C" void kernel_launch(void* const* d_in, const int* in_sizes, int n_in,
                              void* d_out, int out_size)
{
    const float* x = (const float*)d_in[0];
    const float* W = (const float*)d_in[1];
    float* out = (float*)d_out;

    float2 *p0 = nullptr, *p1 = nullptr;
    cudaGetSymbolAddress((void**)&p0, g_p0);
    cudaGetSymbolAddress((void**)&p1, g_p1);

    pack_w<<<1, 256>>>(W);

    dim3 grid(8, 64, 16);   // 1024/128 cols, 512/8 pair-row tiles, 16 images
    dim3 block(128);

    // s0: normal x -> paired p0
    ca_step<false, true><<<grid, block>>>(x, nullptr, nullptr, p0);
    // s1..s8: paired ping-pong
    float2* pin = p0;
    float2* pout = p1;
    for (int s = 1; s <= 8; ++s) {
        ca_step<true, true><<<grid, block>>>(nullptr, pin, nullptr, pout);
        float2* t = pin; pin = pout; pout = t;
    }
    // s9: paired pin -> normal d_out
    ca_step<true, false><<<grid, block>>>(nullptr, pin, out, nullptr);
}